// round 14
// baseline (speedup 1.0000x reference)
#include <cuda_runtime.h>
#include <cuda_bf16.h>
#include <cstdint>

// Problem constants
#define BSZ   64
#define NN    512
#define HID   128
#define NL    3
#define ECNT  16384
#define NCOL  8
#define EMBD  16
#define VOCAB 1000
#define ROWS  (BSZ * NN)      // 32768
#define BF    (BSZ * HID)     // 8192

typedef __nv_bfloat16 bf16;
typedef __nv_bfloat162 bf162;

// ---------------------------------------------------------------------------
// Scratch. Activation layout: [n][j], j = b*128+f (ld 8192), aliasing [r][f]
// (r = n*64+b) bit-exactly. A and merged-W live as presplit bf16 hi/lo planes.
// ---------------------------------------------------------------------------
__device__ __align__(16) float g_A[NN * NN];
__device__ __align__(16) float g_deg[NN];
__device__ __align__(16) float g_X[NN * BF];            // layer-0 input, [n][j]
__device__ __align__(16) float g_AX[ROWS * HID];        // A@x, [r][f] == [n][j]
__device__ __align__(16) float g_H[ROWS * HID];         // Hn,  [r][f] == [n][j]
__device__ __align__(16) float g_bm[NL * 256];
__device__ __align__(16) float g_comb[BSZ * NL * HID];
__device__ __align__(16) bf16  g_Ah[NN * NN];
__device__ __align__(16) bf16  g_Al[NN * NN];
__device__ __align__(16) bf16  g_Wh[NL * 256 * HID];    // interleaved rows (2f=z,2f+1=h), cols i
__device__ __align__(16) bf16  g_Wl[NL * 256 * HID];

// ---------------------------------------------------------------------------
// Helpers
// ---------------------------------------------------------------------------
__device__ __forceinline__ uint32_t s2u(const void* p) {
    uint32_t a;
    asm("{ .reg .u64 t; cvta.to.shared.u64 t, %1; cvt.u32.u64 %0, t; }" : "=r"(a) : "l"(p));
    return a;
}
__device__ __forceinline__ void ldsm4(uint32_t* r, uint32_t addr) {
    asm volatile("ldmatrix.sync.aligned.m8n8.x4.shared.b16 {%0,%1,%2,%3}, [%4];"
                 : "=r"(r[0]), "=r"(r[1]), "=r"(r[2]), "=r"(r[3]) : "r"(addr));
}
__device__ __forceinline__ void ldsm4t(uint32_t* r, uint32_t addr) {
    asm volatile("ldmatrix.sync.aligned.m8n8.x4.trans.shared.b16 {%0,%1,%2,%3}, [%4];"
                 : "=r"(r[0]), "=r"(r[1]), "=r"(r[2]), "=r"(r[3]) : "r"(addr));
}
__device__ __forceinline__ void mma16816(float* d, const uint32_t* a, const uint32_t* b) {
    asm volatile(
        "mma.sync.aligned.m16n8k16.row.col.f32.bf16.bf16.f32 "
        "{%0,%1,%2,%3},{%4,%5,%6,%7},{%8,%9},{%0,%1,%2,%3};"
        : "+f"(d[0]), "+f"(d[1]), "+f"(d[2]), "+f"(d[3])
        : "r"(a[0]), "r"(a[1]), "r"(a[2]), "r"(a[3]), "r"(b[0]), "r"(b[1]));
}
__device__ __forceinline__ void cpasync16(uint32_t dst, const void* src) {
    asm volatile("cp.async.cg.shared.global [%0], [%1], 16;" :: "r"(dst), "l"(src));
}
#define CP_COMMIT() asm volatile("cp.async.commit_group;" ::: "memory")
#define CP_WAIT0()  asm volatile("cp.async.wait_group 0;" ::: "memory")

// bf16 2-term split of a float4, stored to hi/lo smem arrays at elem offset pos
__device__ __forceinline__ void split_store(bf16* hi, bf16* lo, int pos, float4 v) {
    bf162 h0 = __float22bfloat162_rn(make_float2(v.x, v.y));
    bf162 h1 = __float22bfloat162_rn(make_float2(v.z, v.w));
    float2 f0 = __bfloat1622float2(h0), f1 = __bfloat1622float2(h1);
    bf162 l0 = __float22bfloat162_rn(make_float2(v.x - f0.x, v.y - f0.y));
    bf162 l1 = __float22bfloat162_rn(make_float2(v.z - f1.x, v.w - f1.y));
    *(bf162*)(hi + pos)     = h0;
    *(bf162*)(hi + pos + 2) = h1;
    *(bf162*)(lo + pos)     = l0;
    *(bf162*)(lo + pos + 2) = l1;
}
__device__ __forceinline__ void split1(float x, bf16& h, bf16& l) {
    h = __float2bfloat16(x);
    l = __float2bfloat16(x - __bfloat162float(h));
}
// fast sigmoid/tanh pieces (inputs are O(1) for this data; no overflow range)
__device__ __forceinline__ float gate_val(float zl, float hl) {
    float ez  = __expf(-zl);
    float omz = __fdividef(ez, 1.f + ez);          // 1 - sigmoid(zl)
    float e2  = __expf(2.f * hl);
    float th  = 1.f - __fdividef(2.f, e2 + 1.f);   // tanh(hl)
    return omz * th;
}

// ---------------------------------------------------------------------------
// Graph normalization + scratch zeroing (comb zeroed every replay; readout
// accumulates with atomics)
// ---------------------------------------------------------------------------
__global__ void k_zeroA() {
    int i = blockIdx.x * blockDim.x + threadIdx.x;
    if (i < NN * NN) g_A[i] = 0.f;
    if (i < NN) g_deg[i] = 1.f;
    if (i < BSZ * NL * HID) g_comb[i] = 0.f;
}
__global__ void k_deg(const int* __restrict__ edge) {
    int e = blockIdx.x * blockDim.x + threadIdx.x;
    if (e < ECNT) atomicAdd(&g_deg[edge[ECNT + e]], 1.f);
}

// ---------------------------------------------------------------------------
// Merged: adjacency build (blocks 0..65) + embedding lookup (blocks 66..1089)
// ---------------------------------------------------------------------------
#define BUILD_BLKS 66    // 66*256 = 16896 = ECNT + NN exactly
__global__ void k_build_embed(const int* __restrict__ edge,
                              const int* __restrict__ xseq,
                              const float* __restrict__ emb) {
    if (blockIdx.x < BUILD_BLKS) {
        int e = blockIdx.x * 256 + threadIdx.x;
        if (e < ECNT) {
            int s = edge[e];
            int d = edge[ECNT + e];
            atomicAdd(&g_A[d * NN + s], rsqrtf(g_deg[s]) * rsqrtf(g_deg[d]));
        } else {
            int n = e - ECNT;
            atomicAdd(&g_A[n * NN + n], 1.f / g_deg[n]);
        }
    } else {
        int t = (blockIdx.x - BUILD_BLKS) * 256 + threadIdx.x;
        int c = t & 7;
        int b = (t >> 3) & 63;
        int n = t >> 9;
        int v = xseq[(b * NN + n) * NCOL + c];
        const float4* e4 = (const float4*)(emb + ((long long)(c * VOCAB + v)) * EMBD);
        float4* o = (float4*)(g_X + (long long)n * BF + b * 128 + c * 16);
        o[0] = e4[0]; o[1] = e4[1]; o[2] = e4[2]; o[3] = e4[3];
    }
}

// ---------------------------------------------------------------------------
// Split adjacency to bf16 hi/lo planes (once per replay)
// ---------------------------------------------------------------------------
__global__ void k_splitA() {
    int i = blockIdx.x * blockDim.x + threadIdx.x;
    if (i >= NN * NN) return;
    split1(g_A[i], g_Ah[i], g_Al[i]);
}

// ---------------------------------------------------------------------------
// Fused weight merges (write presplit bf16 planes) + merged bias (grid (2,2,7))
// ---------------------------------------------------------------------------
__global__ void __launch_bounds__(256) k_gemm64f(
    const float* __restrict__ conv_w,
    const float* __restrict__ lin_w,
    const float* __restrict__ conv_b,
    const float* __restrict__ lin_b)
{
    if (blockIdx.z == 6) {
        int l = blockIdx.y * 2 + blockIdx.x;
        if (l < NL) {
            int o = threadIdx.x;
            int f = o >> 1;
            int gg = (o & 1) ? 2 : 0;
            const float* cb = conv_b + (l * 3 + gg) * 128;
            const float* lw = lin_w + (l * 3 + gg) * 32768;
            float s = lin_b[(l * 3 + gg) * 128 + f];
            for (int k = 0; k < 128; k++) s += cb[k] * lw[k * 128 + f];
            g_bm[l * 256 + o] = s;
        }
        return;
    }

    const int l = blockIdx.z >> 1;
    const int half = blockIdx.z & 1;
    const int g = half ? 2 : 0;
    const float* Ag = conv_w + (l * 3 + g) * 16384;
    const float* Bg = lin_w  + (l * 3 + g) * 32768;

    const int tileN = blockIdx.x * 64;
    const int tileM = blockIdx.y * 64;
    __shared__ float As[16][65];
    __shared__ float Bs[16][64];
    const int tid = threadIdx.x;
    const int tx = tid & 15, ty = tid >> 4;
    float acc[4][4] = {};
    for (int k0 = 0; k0 < 128; k0 += 16) {
        #pragma unroll
        for (int i = 0; i < 4; i++) {
            int idx = tid + i * 256;
            int m = idx >> 4, k = idx & 15;
            As[k][m] = Ag[(tileM + m) * 128 + (k0 + k)];
        }
        #pragma unroll
        for (int i = 0; i < 4; i++) {
            int idx = tid + i * 256;
            int k = idx >> 6, n = idx & 63;
            Bs[k][n] = Bg[(k0 + k) * 128 + (tileN + n)];
        }
        __syncthreads();
        #pragma unroll
        for (int k = 0; k < 16; k++) {
            float a[4], b[4];
            #pragma unroll
            for (int i = 0; i < 4; i++) a[i] = As[k][ty * 4 + i];
            #pragma unroll
            for (int j = 0; j < 4; j++) b[j] = Bs[k][tx * 4 + j];
            #pragma unroll
            for (int i = 0; i < 4; i++)
                #pragma unroll
                for (int j = 0; j < 4; j++) acc[i][j] += a[i] * b[j];
        }
        __syncthreads();
    }
    #pragma unroll
    for (int i = 0; i < 4; i++)
        #pragma unroll
        for (int j = 0; j < 4; j++) {
            long long off = (long long)l * 32768 +
                (long long)((tileN + tx * 4 + j) * 2 + half) * 128 + (tileM + ty * 4 + i);
            bf16 h, lo;
            split1(acc[i][j], h, lo);
            g_Wh[off] = h;
            g_Wl[off] = lo;
        }
}

// ---------------------------------------------------------------------------
// Tensor-core GEMM, 256 threads, 8 warps (2m x 4n), warp tile 64x32, 2 CTAs/SM.
//  BTRANS=1 (GEMM1): A = presplit planes (cp.async), B = fp32 [k][n] (trans,
//                    inline split). lda = plane pitch (512).
//  BTRANS=0 (GEMM2): A = fp32 [m][k] (inline split), B = presplit planes
//                    (cp.async), ldb = plane pitch (128).
//  FUSEGATE=1: N interleaved z|h; gate -> C[m*ldc + n/2], plus fused node-mean
//              readout into combL via atomicAdd.
// CTA tile 128x128, K-chunk 16, double-buffered, 1 sync/chunk.
// ---------------------------------------------------------------------------
#define PA 24
#define ASZE (128 * PA)

template<int BTRANS, int FUSEGATE>
__global__ void __launch_bounds__(256, 2) k_mma(
    const float* __restrict__ Af, int lda,
    const bf16* __restrict__ APh, const bf16* __restrict__ APl,
    const float* __restrict__ Bf, int ldb,
    const bf16* __restrict__ BPh, const bf16* __restrict__ BPl,
    float* __restrict__ C, int ldc,
    int K, const float* __restrict__ bias, float* __restrict__ combL)
{
    constexpr int PB   = BTRANS ? 136 : 24;
    constexpr int BSZE = BTRANS ? 16 * 136 : 128 * 24;
    __shared__ __align__(16) bf16 smA[2][2][ASZE];
    __shared__ __align__(16) bf16 smB[2][2][BSZE];

    const int tid = threadIdx.x;
    const int lane = tid & 31, w = tid >> 5;
    const int wm = w & 1, wn = w >> 1;
    const int tileM = blockIdx.y * 128, tileN = blockIdx.x * 128;

    const uint32_t sa0 = s2u(&smA[0][0][0]);
    const uint32_t sb0 = s2u(&smB[0][0][0]);

    // --- presplit operand (cp.async): 1 x 16B per plane per thread per chunk
    const int prow = tid >> 1, pkq = tid & 1;
    const bf16 *Ph, *Pl;
    if (BTRANS) {
        Ph = APh + (long long)(tileM + prow) * lda + pkq * 8;
        Pl = APl + (long long)(tileM + prow) * lda + pkq * 8;
    } else {
        Ph = BPh + (long long)(tileN + prow) * ldb + pkq * 8;
        Pl = BPl + (long long)(tileN + prow) * ldb + pkq * 8;
    }
    const int pPos = prow * (BTRANS ? PA : PB) + pkq * 8;   // both == 24 pitch
    const uint32_t pbase0 = BTRANS ? sa0 : sb0;
    const uint32_t pplane = BTRANS ? (uint32_t)(ASZE * 2) : (uint32_t)(BSZE * 2);
    const uint32_t pbufst = 2 * pplane;

    // --- fp32 operand (inline split): 2 float4 per thread per chunk
    int frow[2], fcq[2];
    #pragma unroll
    for (int i = 0; i < 2; i++) {
        int idx = tid + i * 256;
        if (BTRANS) { frow[i] = idx >> 5; fcq[i] = idx & 31; }   // B: 16 k-rows x 32 f4
        else        { frow[i] = idx >> 2; fcq[i] = idx & 3;  }   // A: 128 rows x 4 f4
    }
    const float* Fp[2];
    int fPos[2];
    #pragma unroll
    for (int i = 0; i < 2; i++) {
        if (BTRANS) {
            Fp[i] = Bf + (long long)frow[i] * ldb + tileN + fcq[i] * 4;
            fPos[i] = frow[i] * PB + fcq[i] * 4;
        } else {
            Fp[i] = Af + (long long)(tileM + frow[i]) * lda + fcq[i] * 4;
            fPos[i] = frow[i] * PA + fcq[i] * 4;
        }
    }
    bf16* fHi0 = BTRANS ? smB[0][0] : smA[0][0];
    bf16* fLo0 = BTRANS ? smB[0][1] : smA[0][1];
    bf16* fHi1 = BTRANS ? smB[1][0] : smA[1][0];
    bf16* fLo1 = BTRANS ? smB[1][1] : smA[1][1];
    const long long fstep = BTRANS ? 16LL * ldb : 16LL;

    const int KC = K >> 4;

    float acc[4][4][4];
    #pragma unroll
    for (int i = 0; i < 4; i++)
        #pragma unroll
        for (int j = 0; j < 4; j++)
            #pragma unroll
            for (int q = 0; q < 4; q++) acc[i][j][q] = 0.f;

    const int arow_l = wm * 64 + (lane & 15);
    const int acol_l = (lane >> 4) * 8;
    const int brow_l = wn * 32 + ((lane >> 4) & 1) * 8 + (lane & 7);
    const int bcol_l = ((lane >> 3) & 1) * 8;
    const int tkrow_l = ((lane >> 3) & 1) * 8 + (lane & 7);
    const int tnoff_l = wn * 32 + ((lane >> 4) & 1) * 8;

    // prologue: chunk 0 -> buffer 0
    cpasync16(pbase0 + pPos * 2, Ph);
    cpasync16(pbase0 + pplane + pPos * 2, Pl);
    CP_COMMIT();
    float4 rf[2];
    #pragma unroll
    for (int i = 0; i < 2; i++) rf[i] = *(const float4*)Fp[i];
    #pragma unroll
    for (int i = 0; i < 2; i++) split_store(fHi0, fLo0, fPos[i], rf[i]);
    CP_WAIT0();

    for (int c = 0; c < KC; c++) {
        __syncthreads();
        const int buf = c & 1;
        if (c + 1 < KC) {
            // async prefetch of presplit operand into buf^1
            uint32_t pb = pbase0 + (buf ^ 1) * pbufst + pPos * 2;
            cpasync16(pb, Ph + (c + 1) * 16);
            cpasync16(pb + pplane, Pl + (c + 1) * 16);
            CP_COMMIT();
            #pragma unroll
            for (int i = 0; i < 2; i++)
                rf[i] = *(const float4*)(Fp[i] + (c + 1) * fstep);
        }

        const uint32_t ba = sa0 + buf * (2 * ASZE * 2);
        const uint32_t bb = sb0 + buf * (2 * BSZE * 2);
        uint32_t ah[4][4], bh[2][4], bl[2][4];
        #pragma unroll
        for (int i = 0; i < 4; i++)
            ldsm4(ah[i], ba + (uint32_t)((arow_l + i * 16) * PA + acol_l) * 2);
        #pragma unroll
        for (int p = 0; p < 2; p++) {
            if (BTRANS) {
                ldsm4t(bh[p], bb + (uint32_t)(tkrow_l * PB + tnoff_l + p * 16) * 2);
                ldsm4t(bl[p], bb + (uint32_t)(BSZE * 2) + (uint32_t)(tkrow_l * PB + tnoff_l + p * 16) * 2);
            } else {
                ldsm4(bh[p], bb + (uint32_t)((brow_l + p * 16) * PB + bcol_l) * 2);
                ldsm4(bl[p], bb + (uint32_t)(BSZE * 2) + (uint32_t)((brow_l + p * 16) * PB + bcol_l) * 2);
            }
        }
        #pragma unroll
        for (int i = 0; i < 4; i++)
            #pragma unroll
            for (int nt = 0; nt < 4; nt++)
                mma16816(acc[i][nt], ah[i], &bh[nt >> 1][(nt & 1) * 2]);
        #pragma unroll
        for (int i = 0; i < 4; i++)
            #pragma unroll
            for (int nt = 0; nt < 4; nt++)
                mma16816(acc[i][nt], ah[i], &bl[nt >> 1][(nt & 1) * 2]);
        #pragma unroll
        for (int i = 0; i < 4; i++)     // reuse ah for A-lo
            ldsm4(ah[i], ba + (uint32_t)(ASZE * 2) + (uint32_t)((arow_l + i * 16) * PA + acol_l) * 2);
        #pragma unroll
        for (int i = 0; i < 4; i++)
            #pragma unroll
            for (int nt = 0; nt < 4; nt++)
                mma16816(acc[i][nt], ah[i], &bh[nt >> 1][(nt & 1) * 2]);

        if (c + 1 < KC) {
            bf16* hi = (buf ^ 1) ? fHi1 : fHi0;
            bf16* lo = (buf ^ 1) ? fLo1 : fLo0;
            #pragma unroll
            for (int i = 0; i < 2; i++) split_store(hi, lo, fPos[i], rf[i]);
            CP_WAIT0();
        }
    }

    // Epilogue
    if (FUSEGATE) {
        #pragma unroll
        for (int i = 0; i < 4; i++) {
            int m = tileM + wm * 64 + i * 16 + (lane >> 2);
            #pragma unroll
            for (int nt = 0; nt < 4; nt++) {
                int n = tileN + wn * 32 + nt * 8 + (lane & 3) * 2;
                int f = n >> 1;
                float bz = bias[n], bh2 = bias[n + 1];
                float hv0 = gate_val(acc[i][nt][0] + bz, acc[i][nt][1] + bh2);
                float hv1 = gate_val(acc[i][nt][2] + bz, acc[i][nt][3] + bh2);
                C[(long long)m * ldc + f]       = hv0;
                C[(long long)(m + 8) * ldc + f] = hv1;
                atomicAdd(&combL[(m & 63) * (NL * HID) + f],       hv0 * (1.f / NN));
                atomicAdd(&combL[((m + 8) & 63) * (NL * HID) + f], hv1 * (1.f / NN));
            }
        }
    } else {
        #pragma unroll
        for (int i = 0; i < 4; i++) {
            int m = tileM + wm * 64 + i * 16 + (lane >> 2);
            #pragma unroll
            for (int nt = 0; nt < 4; nt++) {
                int n = tileN + wn * 32 + nt * 8 + (lane & 3) * 2;
                float2 v0 = {acc[i][nt][0], acc[i][nt][1]};
                float2 v1 = {acc[i][nt][2], acc[i][nt][3]};
                *(float2*)(C + (long long)m * ldc + n)       = v0;
                *(float2*)(C + (long long)(m + 8) * ldc + n) = v1;
            }
        }
    }
}

// ---------------------------------------------------------------------------
// Classifier
// ---------------------------------------------------------------------------
__global__ void k_cls(const float* __restrict__ w1, const float* __restrict__ b1,
                      const float* __restrict__ w2, const float* __restrict__ b2,
                      float* __restrict__ out) {
    int b = blockIdx.x;
    int o = threadIdx.x;
    __shared__ float hid[HID];
    float s = b1[o];
    const float* cb = g_comb + b * (NL * HID);
    for (int k = 0; k < NL * HID; k++) s += cb[k] * w1[k * HID + o];
    hid[o] = fmaxf(s, 0.f);
    __syncthreads();
    if (o < 2) {
        float t = b2[o];
        for (int k = 0; k < HID; k++) t += hid[k] * w2[k * 2 + o];
        out[b * 2 + o] = t;
    }
}

// ---------------------------------------------------------------------------
// Launch
// ---------------------------------------------------------------------------
extern "C" void kernel_launch(void* const* d_in, const int* in_sizes, int n_in,
                              void* d_out, int out_size) {
    const int*   x_seq  = (const int*)  d_in[0];
    const int*   edge   = (const int*)  d_in[1];
    const float* emb    = (const float*)d_in[2];
    const float* conv_w = (const float*)d_in[3];
    const float* conv_b = (const float*)d_in[4];
    const float* lin_w  = (const float*)d_in[5];
    const float* lin_b  = (const float*)d_in[6];
    const float* w1     = (const float*)d_in[7];
    const float* b1     = (const float*)d_in[8];
    const float* w2     = (const float*)d_in[9];
    const float* b2     = (const float*)d_in[10];
    float* out = (float*)d_out;

    float *pX, *pAX, *pH, *pBm, *pComb;
    bf16 *pAh, *pAl, *pWh, *pWl;
    cudaGetSymbolAddress((void**)&pX,    g_X);
    cudaGetSymbolAddress((void**)&pAX,   g_AX);
    cudaGetSymbolAddress((void**)&pH,    g_H);
    cudaGetSymbolAddress((void**)&pBm,   g_bm);
    cudaGetSymbolAddress((void**)&pComb, g_comb);
    cudaGetSymbolAddress((void**)&pAh,   g_Ah);
    cudaGetSymbolAddress((void**)&pAl,   g_Al);
    cudaGetSymbolAddress((void**)&pWh,   g_Wh);
    cudaGetSymbolAddress((void**)&pWl,   g_Wl);

    // 0: zero adjacency + deg init + comb zero
    k_zeroA<<<(NN * NN + 255) / 256, 256>>>();
    // 1: degree accumulation
    k_deg<<<(ECNT + 255) / 256, 256>>>(edge);
    // 2: adjacency build + embedding (merged)
    k_build_embed<<<BUILD_BLKS + (NN * BSZ * NCOL) / 256, 256>>>(edge, x_seq, emb);
    // 3: adjacency -> bf16 hi/lo planes
    k_splitA<<<(NN * NN + 255) / 256, 256>>>();

    for (int l = 0; l < NL; l++) {
        const float* xin = (l == 0) ? pX : pH;   // [n][j], ld 8192

        // GEMM1: AX[m=node][j] = sum_n A[m][n] * Xin[n][j]   (M=512,N=8192,K=512)
        k_mma<1, 0><<<dim3(64, 4), 256>>>(
            nullptr, NN, pAh, pAl,
            xin, BF, nullptr, nullptr,
            pAX, BF, NN, nullptr, nullptr);

        if (l == 0) {
            // Weight merges (presplit planes) + merged bias
            k_gemm64f<<<dim3(2, 2, 7), 256>>>(conv_w, lin_w, conv_b, lin_b);
        }

        // GEMM2 + fused gate + fused readout  (M=32768, N=256 interleaved, K=128)
        k_mma<0, 1><<<dim3(2, 256), 256>>>(
            pAX, HID, nullptr, nullptr,
            nullptr, HID, pWh + l * 32768, pWl + l * 32768,
            pH, HID, HID, pBm + l * 256, pComb + l * HID);
    }

    k_cls<<<BSZ, HID>>>(w1, b1, w2, b2, out);
}

// round 15
// speedup vs baseline: 1.0627x; 1.0627x over previous
#include <cuda_runtime.h>
#include <cuda_bf16.h>
#include <cstdint>

// Problem constants
#define BSZ   64
#define NN    512
#define HID   128
#define NL    3
#define ECNT  16384
#define NCOL  8
#define EMBD  16
#define VOCAB 1000
#define ROWS  (BSZ * NN)      // 32768
#define BF    (BSZ * HID)     // 8192

typedef __nv_bfloat16 bf16;
typedef __nv_bfloat162 bf162;

// ---------------------------------------------------------------------------
// Scratch. Activation layout: [n][j], j = b*128+f (ld 8192), aliasing [r][f]
// (r = n*64+b) bit-exactly. Adjacency additionally lives as presplit bf16
// hi/lo planes (build-once constant; GEMM1 streams it via cp.async).
// ---------------------------------------------------------------------------
__device__ __align__(16) float g_A[NN * NN];
__device__ __align__(16) float g_deg[NN];
__device__ __align__(16) float g_X[NN * BF];            // layer-0 input, [n][j]
__device__ __align__(16) float g_AX[ROWS * HID];        // A@x, [r][f] == [n][j]
__device__ __align__(16) float g_H[ROWS * HID];         // Hn,  [r][f] == [n][j]
__device__ __align__(16) float g_WmI[NL * 256 * HID];   // merged W, interleaved rows (2f=z,2f+1=h)
__device__ __align__(16) float g_bm[NL * 256];
__device__ __align__(16) float g_comb[BSZ * NL * HID];
__device__ __align__(16) bf16  g_Ah[NN * NN];
__device__ __align__(16) bf16  g_Al[NN * NN];

// ---------------------------------------------------------------------------
// Helpers
// ---------------------------------------------------------------------------
__device__ __forceinline__ uint32_t s2u(const void* p) {
    uint32_t a;
    asm("{ .reg .u64 t; cvta.to.shared.u64 t, %1; cvt.u32.u64 %0, t; }" : "=r"(a) : "l"(p));
    return a;
}
__device__ __forceinline__ void ldsm4(uint32_t* r, uint32_t addr) {
    asm volatile("ldmatrix.sync.aligned.m8n8.x4.shared.b16 {%0,%1,%2,%3}, [%4];"
                 : "=r"(r[0]), "=r"(r[1]), "=r"(r[2]), "=r"(r[3]) : "r"(addr));
}
__device__ __forceinline__ void ldsm4t(uint32_t* r, uint32_t addr) {
    asm volatile("ldmatrix.sync.aligned.m8n8.x4.trans.shared.b16 {%0,%1,%2,%3}, [%4];"
                 : "=r"(r[0]), "=r"(r[1]), "=r"(r[2]), "=r"(r[3]) : "r"(addr));
}
__device__ __forceinline__ void mma16816(float* d, const uint32_t* a, const uint32_t* b) {
    asm volatile(
        "mma.sync.aligned.m16n8k16.row.col.f32.bf16.bf16.f32 "
        "{%0,%1,%2,%3},{%4,%5,%6,%7},{%8,%9},{%0,%1,%2,%3};"
        : "+f"(d[0]), "+f"(d[1]), "+f"(d[2]), "+f"(d[3])
        : "r"(a[0]), "r"(a[1]), "r"(a[2]), "r"(a[3]), "r"(b[0]), "r"(b[1]));
}
__device__ __forceinline__ void cpasync16(uint32_t dst, const void* src) {
    asm volatile("cp.async.cg.shared.global [%0], [%1], 16;" :: "r"(dst), "l"(src));
}
#define CP_COMMIT() asm volatile("cp.async.commit_group;" ::: "memory")
#define CP_WAIT0()  asm volatile("cp.async.wait_group 0;" ::: "memory")

// bf16 2-term split of a float4, stored to hi/lo smem arrays at elem offset pos
__device__ __forceinline__ void split_store(bf16* hi, bf16* lo, int pos, float4 v) {
    bf162 h0 = __float22bfloat162_rn(make_float2(v.x, v.y));
    bf162 h1 = __float22bfloat162_rn(make_float2(v.z, v.w));
    float2 f0 = __bfloat1622float2(h0), f1 = __bfloat1622float2(h1);
    bf162 l0 = __float22bfloat162_rn(make_float2(v.x - f0.x, v.y - f0.y));
    bf162 l1 = __float22bfloat162_rn(make_float2(v.z - f1.x, v.w - f1.y));
    *(bf162*)(hi + pos)     = h0;
    *(bf162*)(hi + pos + 2) = h1;
    *(bf162*)(lo + pos)     = l0;
    *(bf162*)(lo + pos + 2) = l1;
}
__device__ __forceinline__ void split1(float x, bf16& h, bf16& l) {
    h = __float2bfloat16(x);
    l = __float2bfloat16(x - __bfloat162float(h));
}
// fast sigmoid/tanh pieces (inputs are O(1) for this data; no overflow range)
__device__ __forceinline__ float gate_val(float zl, float hl) {
    float ez  = __expf(-zl);
    float omz = __fdividef(ez, 1.f + ez);          // 1 - sigmoid(zl)
    float e2  = __expf(2.f * hl);
    float th  = 1.f - __fdividef(2.f, e2 + 1.f);   // tanh(hl)
    return omz * th;
}

// ---------------------------------------------------------------------------
// Graph normalization + scratch zeroing (comb zeroed every replay; readout
// accumulates with atomics)
// ---------------------------------------------------------------------------
__global__ void k_zeroA() {
    int i = blockIdx.x * blockDim.x + threadIdx.x;
    if (i < NN * NN) g_A[i] = 0.f;
    if (i < NN) g_deg[i] = 1.f;
    if (i < BSZ * NL * HID) g_comb[i] = 0.f;
}
__global__ void k_deg(const int* __restrict__ edge) {
    int e = blockIdx.x * blockDim.x + threadIdx.x;
    if (e < ECNT) atomicAdd(&g_deg[edge[ECNT + e]], 1.f);
}

// ---------------------------------------------------------------------------
// Merged: adjacency build (blocks 0..65) + embedding lookup (blocks 66..1089)
// ---------------------------------------------------------------------------
#define BUILD_BLKS 66    // 66*256 = 16896 = ECNT + NN exactly
__global__ void k_build_embed(const int* __restrict__ edge,
                              const int* __restrict__ xseq,
                              const float* __restrict__ emb) {
    if (blockIdx.x < BUILD_BLKS) {
        int e = blockIdx.x * 256 + threadIdx.x;
        if (e < ECNT) {
            int s = edge[e];
            int d = edge[ECNT + e];
            atomicAdd(&g_A[d * NN + s], rsqrtf(g_deg[s]) * rsqrtf(g_deg[d]));
        } else {
            int n = e - ECNT;
            atomicAdd(&g_A[n * NN + n], 1.f / g_deg[n]);
        }
    } else {
        int t = (blockIdx.x - BUILD_BLKS) * 256 + threadIdx.x;
        int c = t & 7;
        int b = (t >> 3) & 63;
        int n = t >> 9;
        int v = xseq[(b * NN + n) * NCOL + c];
        const float4* e4 = (const float4*)(emb + ((long long)(c * VOCAB + v)) * EMBD);
        float4* o = (float4*)(g_X + (long long)n * BF + b * 128 + c * 16);
        o[0] = e4[0]; o[1] = e4[1]; o[2] = e4[2]; o[3] = e4[3];
    }
}

// ---------------------------------------------------------------------------
// Split adjacency to bf16 hi/lo planes (once per replay)
// ---------------------------------------------------------------------------
__global__ void k_splitA() {
    int i = blockIdx.x * blockDim.x + threadIdx.x;
    if (i >= NN * NN) return;
    split1(g_A[i], g_Ah[i], g_Al[i]);
}

// ---------------------------------------------------------------------------
// Fused weight merges + merged bias (grid (2,2,7)) — identical to R12
// ---------------------------------------------------------------------------
__global__ void __launch_bounds__(256) k_gemm64f(
    const float* __restrict__ conv_w,
    const float* __restrict__ lin_w,
    const float* __restrict__ conv_b,
    const float* __restrict__ lin_b,
    float* __restrict__ WmI)
{
    if (blockIdx.z == 6) {
        int l = blockIdx.y * 2 + blockIdx.x;
        if (l < NL) {
            int o = threadIdx.x;
            int f = o >> 1;
            int gg = (o & 1) ? 2 : 0;
            const float* cb = conv_b + (l * 3 + gg) * 128;
            const float* lw = lin_w + (l * 3 + gg) * 32768;
            float s = lin_b[(l * 3 + gg) * 128 + f];
            for (int k = 0; k < 128; k++) s += cb[k] * lw[k * 128 + f];
            g_bm[l * 256 + o] = s;
        }
        return;
    }

    const int l = blockIdx.z >> 1;
    const int half = blockIdx.z & 1;
    const int g = half ? 2 : 0;
    const float* Ag = conv_w + (l * 3 + g) * 16384;
    const float* Bg = lin_w  + (l * 3 + g) * 32768;
    float* Cg = WmI + l * 32768;

    const int tileN = blockIdx.x * 64;
    const int tileM = blockIdx.y * 64;
    __shared__ float As[16][65];
    __shared__ float Bs[16][64];
    const int tid = threadIdx.x;
    const int tx = tid & 15, ty = tid >> 4;
    float acc[4][4] = {};
    for (int k0 = 0; k0 < 128; k0 += 16) {
        #pragma unroll
        for (int i = 0; i < 4; i++) {
            int idx = tid + i * 256;
            int m = idx >> 4, k = idx & 15;
            As[k][m] = Ag[(tileM + m) * 128 + (k0 + k)];
        }
        #pragma unroll
        for (int i = 0; i < 4; i++) {
            int idx = tid + i * 256;
            int k = idx >> 6, n = idx & 63;
            Bs[k][n] = Bg[(k0 + k) * 128 + (tileN + n)];
        }
        __syncthreads();
        #pragma unroll
        for (int k = 0; k < 16; k++) {
            float a[4], b[4];
            #pragma unroll
            for (int i = 0; i < 4; i++) a[i] = As[k][ty * 4 + i];
            #pragma unroll
            for (int j = 0; j < 4; j++) b[j] = Bs[k][tx * 4 + j];
            #pragma unroll
            for (int i = 0; i < 4; i++)
                #pragma unroll
                for (int j = 0; j < 4; j++) acc[i][j] += a[i] * b[j];
        }
        __syncthreads();
    }
    #pragma unroll
    for (int i = 0; i < 4; i++)
        #pragma unroll
        for (int j = 0; j < 4; j++)
            Cg[(long long)((tileN + tx * 4 + j) * 2 + half) * 128 + (tileM + ty * 4 + i)] = acc[i][j];
}

// ---------------------------------------------------------------------------
// Tensor-core GEMM, 256 threads, 8 warps (2m x 4n), warp tile 64x32, 2 CTAs/SM.
//  APRE=1: A comes from presplit bf16 planes via cp.async (GEMM1).
//  APRE=0: A fp32 [m][k], inline split (GEMM2).
//  BTRANS=1: B fp32 [k][n] n-contig (ldmatrix.trans); BTRANS=0: B fp32 [n][k].
//  FUSEGATE=1: N interleaved z|h; gate -> C[m*ldc + n/2].
// CTA tile 128x128, K-chunk 16, double-buffered, 1 sync/chunk.
// ---------------------------------------------------------------------------
#define PA 24
#define ASZE (128 * PA)

template<int APRE, int BTRANS, int FUSEGATE>
__global__ void __launch_bounds__(256, 2) k_mma(
    const float* __restrict__ Af,
    const bf16* __restrict__ APh, const bf16* __restrict__ APl, int lda,
    const float* __restrict__ Bf, int ldb,
    float* __restrict__ C, int ldc,
    int K, const float* __restrict__ bias)
{
    constexpr int PB   = BTRANS ? 136 : 24;
    constexpr int BSZE = BTRANS ? 16 * 136 : 128 * 24;
    __shared__ __align__(16) bf16 smA[2][2][ASZE];
    __shared__ __align__(16) bf16 smB[2][2][BSZE];

    const int tid = threadIdx.x;
    const int lane = tid & 31, w = tid >> 5;
    const int wm = w & 1, wn = w >> 1;
    const int tileM = blockIdx.y * 128, tileN = blockIdx.x * 128;

    const uint32_t sa0 = s2u(&smA[0][0][0]);
    const uint32_t sb0 = s2u(&smB[0][0][0]);
    constexpr uint32_t APL = (uint32_t)(ASZE * 2);   // bytes per A plane
    constexpr uint32_t BPL = (uint32_t)(BSZE * 2);

    // --- A loader ---
    // APRE=1: cp.async 16B per plane per thread (128 rows x 16 k)
    const int prow = tid >> 1, pkq = tid & 1;
    const bf16 *Ph = nullptr, *Pl = nullptr;
    if (APRE) {
        Ph = APh + (long long)(tileM + prow) * lda + pkq * 8;
        Pl = APl + (long long)(tileM + prow) * lda + pkq * 8;
    }
    const uint32_t pByte = (uint32_t)(prow * PA + pkq * 8) * 2;
    // APRE=0: 2 float4 per thread
    int arow2[2], akq2[2];
    const float* Ap2[2] = {nullptr, nullptr};
    #pragma unroll
    for (int i = 0; i < 2; i++) {
        int idx = tid + i * 256;
        arow2[i] = idx >> 2; akq2[i] = idx & 3;
        if (!APRE) Ap2[i] = Af + (long long)(tileM + arow2[i]) * lda + akq2[i] * 4;
    }

    // --- B loader (fp32, inline split) ---
    int brow2[2], bcq2[2];
    const float* Bp2[2];
    #pragma unroll
    for (int i = 0; i < 2; i++) {
        int idx = tid + i * 256;
        if (BTRANS) { brow2[i] = idx >> 5; bcq2[i] = idx & 31; }
        else        { brow2[i] = idx >> 2; bcq2[i] = idx & 3;  }
        if (BTRANS) Bp2[i] = Bf + (long long)brow2[i] * ldb + tileN + bcq2[i] * 4;
        else        Bp2[i] = Bf + (long long)(tileN + brow2[i]) * ldb + bcq2[i] * 4;
    }
    const long long bstep = BTRANS ? 16LL * ldb : 16LL;

    const int KC = K >> 4;
    float4 ra[2], rb[2];

    float acc[4][4][4];
    #pragma unroll
    for (int i = 0; i < 4; i++)
        #pragma unroll
        for (int j = 0; j < 4; j++)
            #pragma unroll
            for (int q = 0; q < 4; q++) acc[i][j][q] = 0.f;

    const int arow_l = wm * 64 + (lane & 15);
    const int acol_l = (lane >> 4) * 8;
    const int brow_l = wn * 32 + ((lane >> 4) & 1) * 8 + (lane & 7);
    const int bcol_l = ((lane >> 3) & 1) * 8;
    const int tkrow_l = ((lane >> 3) & 1) * 8 + (lane & 7);
    const int tnoff_l = wn * 32 + ((lane >> 4) & 1) * 8;

    // prologue: chunk 0 -> buffer 0
    if (APRE) {
        cpasync16(sa0 + pByte, Ph);
        cpasync16(sa0 + APL + pByte, Pl);
        CP_COMMIT();
    } else {
        #pragma unroll
        for (int i = 0; i < 2; i++) {
            ra[i] = *(const float4*)Ap2[i];
            split_store(smA[0][0], smA[0][1], arow2[i] * PA + akq2[i] * 4, ra[i]);
        }
    }
    #pragma unroll
    for (int i = 0; i < 2; i++) {
        rb[i] = *(const float4*)Bp2[i];
        split_store(smB[0][0], smB[0][1], brow2[i] * PB + bcq2[i] * 4, rb[i]);
    }
    if (APRE) CP_WAIT0();

    for (int c = 0; c < KC; c++) {
        __syncthreads();
        const int buf = c & 1;
        if (c + 1 < KC) {
            if (APRE) {
                uint32_t pb = sa0 + (buf ^ 1) * (2 * APL) + pByte;
                cpasync16(pb, Ph + (c + 1) * 16);
                cpasync16(pb + APL, Pl + (c + 1) * 16);
                CP_COMMIT();
            } else {
                #pragma unroll
                for (int i = 0; i < 2; i++)
                    ra[i] = *(const float4*)(Ap2[i] + (c + 1) * 16);
            }
            #pragma unroll
            for (int i = 0; i < 2; i++)
                rb[i] = *(const float4*)(Bp2[i] + (c + 1) * bstep);
        }

        const uint32_t ba = sa0 + buf * (2 * APL);
        const uint32_t bb = sb0 + buf * (2 * BPL);
        uint32_t ah[4][4], bh[2][4], bl[2][4];
        #pragma unroll
        for (int i = 0; i < 4; i++)
            ldsm4(ah[i], ba + (uint32_t)((arow_l + i * 16) * PA + acol_l) * 2);
        #pragma unroll
        for (int p = 0; p < 2; p++) {
            if (BTRANS) {
                ldsm4t(bh[p], bb + (uint32_t)(tkrow_l * PB + tnoff_l + p * 16) * 2);
                ldsm4t(bl[p], bb + BPL + (uint32_t)(tkrow_l * PB + tnoff_l + p * 16) * 2);
            } else {
                ldsm4(bh[p], bb + (uint32_t)((brow_l + p * 16) * PB + bcol_l) * 2);
                ldsm4(bl[p], bb + BPL + (uint32_t)((brow_l + p * 16) * PB + bcol_l) * 2);
            }
        }
        #pragma unroll
        for (int i = 0; i < 4; i++)
            #pragma unroll
            for (int nt = 0; nt < 4; nt++)
                mma16816(acc[i][nt], ah[i], &bh[nt >> 1][(nt & 1) * 2]);
        #pragma unroll
        for (int i = 0; i < 4; i++)
            #pragma unroll
            for (int nt = 0; nt < 4; nt++)
                mma16816(acc[i][nt], ah[i], &bl[nt >> 1][(nt & 1) * 2]);
        #pragma unroll
        for (int i = 0; i < 4; i++)     // reuse ah for A-lo
            ldsm4(ah[i], ba + APL + (uint32_t)((arow_l + i * 16) * PA + acol_l) * 2);
        #pragma unroll
        for (int i = 0; i < 4; i++)
            #pragma unroll
            for (int nt = 0; nt < 4; nt++)
                mma16816(acc[i][nt], ah[i], &bh[nt >> 1][(nt & 1) * 2]);

        if (c + 1 < KC) {
            const int nb = buf ^ 1;
            if (!APRE) {
                #pragma unroll
                for (int i = 0; i < 2; i++)
                    split_store(smA[nb][0], smA[nb][1], arow2[i] * PA + akq2[i] * 4, ra[i]);
            }
            #pragma unroll
            for (int i = 0; i < 2; i++)
                split_store(smB[nb][0], smB[nb][1], brow2[i] * PB + bcq2[i] * 4, rb[i]);
            if (APRE) CP_WAIT0();
        }
    }

    // Epilogue
    if (FUSEGATE) {
        #pragma unroll
        for (int i = 0; i < 4; i++) {
            int m = tileM + wm * 64 + i * 16 + (lane >> 2);
            #pragma unroll
            for (int nt = 0; nt < 4; nt++) {
                int n = tileN + wn * 32 + nt * 8 + (lane & 3) * 2;
                int f = n >> 1;
                float bz = bias[n], bh2 = bias[n + 1];
                C[(long long)m * ldc + f]       = gate_val(acc[i][nt][0] + bz, acc[i][nt][1] + bh2);
                C[(long long)(m + 8) * ldc + f] = gate_val(acc[i][nt][2] + bz, acc[i][nt][3] + bh2);
            }
        }
    } else {
        #pragma unroll
        for (int i = 0; i < 4; i++) {
            int m = tileM + wm * 64 + i * 16 + (lane >> 2);
            #pragma unroll
            for (int nt = 0; nt < 4; nt++) {
                int n = tileN + wn * 32 + nt * 8 + (lane & 3) * 2;
                float2 v0 = {acc[i][nt][0], acc[i][nt][1]};
                float2 v1 = {acc[i][nt][2], acc[i][nt][3]};
                *(float2*)(C + (long long)m * ldc + n)       = v0;
                *(float2*)(C + (long long)(m + 8) * ldc + n) = v1;
            }
        }
    }
}

// ---------------------------------------------------------------------------
// Readout: mean over nodes, 8-way parallel over the node dim + atomicAdd.
// g_comb zeroed every replay in k_zeroA.
// ---------------------------------------------------------------------------
__global__ void k_readout(int l) {
    int t = blockIdx.x * blockDim.x + threadIdx.x;   // 0 .. BF*8-1
    if (t >= BF * 8) return;
    int j = t & (BF - 1);
    int part = t >> 13;                  // 0..7, 64 nodes each
    float s = 0.f;
    const float* base = g_H + (long long)part * 64 * BF + j;
    #pragma unroll 8
    for (int n = 0; n < 64; n++) s += base[(long long)n * BF];
    int b = j >> 7, f = j & 127;
    atomicAdd(&g_comb[b * (NL * HID) + l * HID + f], s * (1.f / NN));
}

__global__ void k_cls(const float* __restrict__ w1, const float* __restrict__ b1,
                      const float* __restrict__ w2, const float* __restrict__ b2,
                      float* __restrict__ out) {
    int b = blockIdx.x;
    int o = threadIdx.x;
    __shared__ float hid[HID];
    float s = b1[o];
    const float* cb = g_comb + b * (NL * HID);
    for (int k = 0; k < NL * HID; k++) s += cb[k] * w1[k * HID + o];
    hid[o] = fmaxf(s, 0.f);
    __syncthreads();
    if (o < 2) {
        float t = b2[o];
        for (int k = 0; k < HID; k++) t += hid[k] * w2[k * 2 + o];
        out[b * 2 + o] = t;
    }
}

// ---------------------------------------------------------------------------
// Launch
// ---------------------------------------------------------------------------
extern "C" void kernel_launch(void* const* d_in, const int* in_sizes, int n_in,
                              void* d_out, int out_size) {
    const int*   x_seq  = (const int*)  d_in[0];
    const int*   edge   = (const int*)  d_in[1];
    const float* emb    = (const float*)d_in[2];
    const float* conv_w = (const float*)d_in[3];
    const float* conv_b = (const float*)d_in[4];
    const float* lin_w  = (const float*)d_in[5];
    const float* lin_b  = (const float*)d_in[6];
    const float* w1     = (const float*)d_in[7];
    const float* b1     = (const float*)d_in[8];
    const float* w2     = (const float*)d_in[9];
    const float* b2     = (const float*)d_in[10];
    float* out = (float*)d_out;

    float *pX, *pAX, *pH, *pWmI, *pBm;
    bf16 *pAh, *pAl;
    cudaGetSymbolAddress((void**)&pX,   g_X);
    cudaGetSymbolAddress((void**)&pAX,  g_AX);
    cudaGetSymbolAddress((void**)&pH,   g_H);
    cudaGetSymbolAddress((void**)&pWmI, g_WmI);
    cudaGetSymbolAddress((void**)&pBm,  g_bm);
    cudaGetSymbolAddress((void**)&pAh,  g_Ah);
    cudaGetSymbolAddress((void**)&pAl,  g_Al);

    // 0: zero adjacency + deg init + comb zero
    k_zeroA<<<(NN * NN + 255) / 256, 256>>>();
    // 1: degree accumulation
    k_deg<<<(ECNT + 255) / 256, 256>>>(edge);
    // 2: adjacency build + embedding (merged)
    k_build_embed<<<BUILD_BLKS + (NN * BSZ * NCOL) / 256, 256>>>(edge, x_seq, emb);
    // 3: adjacency -> presplit bf16 planes
    k_splitA<<<(NN * NN + 255) / 256, 256>>>();

    for (int l = 0; l < NL; l++) {
        const float* xin = (l == 0) ? pX : pH;   // [n][j], ld 8192

        // GEMM1: AX[m=node][j] = sum_n A[m][n] * Xin[n][j]   (M=512,N=8192,K=512)
        // A from presplit planes via cp.async
        k_mma<1, 1, 0><<<dim3(64, 4), 256>>>(
            nullptr, pAh, pAl, NN,
            xin, BF, pAX, BF, NN, nullptr);

        if (l == 0) {
            // Weight merges + merged bias (needed before first GEMM2 only)
            k_gemm64f<<<dim3(2, 2, 7), 256>>>(conv_w, lin_w, conv_b, lin_b, pWmI);
        }

        // GEMM2 + fused gate: H[r][f]  (M=32768, N=256 interleaved, K=128)
        k_mma<0, 0, 1><<<dim3(2, 256), 256>>>(
            pAX, nullptr, nullptr, HID,
            pWmI + l * 32768, HID, pH, HID, HID, pBm + l * 256);

        k_readout<<<(BF * 8 + 255) / 256, 256>>>(l);
    }

    k_cls<<<BSZ, HID>>>(w1, b1, w2, b2, out);
}

// round 17
// speedup vs baseline: 1.1513x; 1.0833x over previous
#include <cuda_runtime.h>
#include <cuda_bf16.h>
#include <cstdint>

// Problem constants
#define BSZ   64
#define NN    512
#define HID   128
#define NL    3
#define ECNT  16384
#define NCOL  8
#define EMBD  16
#define VOCAB 1000
#define ROWS  (BSZ * NN)      // 32768
#define BF    (BSZ * HID)     // 8192

typedef __nv_bfloat16 bf16;
typedef __nv_bfloat162 bf162;

// ---------------------------------------------------------------------------
// Scratch. Activation layout: [n][j], j = b*128+f (ld 8192), aliasing [r][f]
// (r = n*64+b) bit-exactly: n*8192 + b*128 + f.
// ---------------------------------------------------------------------------
__device__ __align__(16) float g_A[NN * NN];
__device__ __align__(16) float g_deg[NN];
__device__ __align__(16) float g_X[NN * BF];            // layer-0 input, [n][j]
__device__ __align__(16) float g_AX[ROWS * HID];        // A@x, [r][f] == [n][j]
__device__ __align__(16) float g_H[ROWS * HID];         // Hn,  [r][f] == [n][j]
__device__ __align__(16) float g_WmI[NL * 256 * HID];   // merged W, interleaved rows (2f=z,2f+1=h)
__device__ __align__(16) float g_bm[NL * 256];
__device__ __align__(16) float g_comb[BSZ * NL * HID];

// ---------------------------------------------------------------------------
// Helpers
// ---------------------------------------------------------------------------
__device__ __forceinline__ uint32_t s2u(const void* p) {
    uint32_t a;
    asm("{ .reg .u64 t; cvta.to.shared.u64 t, %1; cvt.u32.u64 %0, t; }" : "=r"(a) : "l"(p));
    return a;
}
__device__ __forceinline__ void ldsm4(uint32_t* r, uint32_t addr) {
    asm volatile("ldmatrix.sync.aligned.m8n8.x4.shared.b16 {%0,%1,%2,%3}, [%4];"
                 : "=r"(r[0]), "=r"(r[1]), "=r"(r[2]), "=r"(r[3]) : "r"(addr));
}
__device__ __forceinline__ void ldsm4t(uint32_t* r, uint32_t addr) {
    asm volatile("ldmatrix.sync.aligned.m8n8.x4.trans.shared.b16 {%0,%1,%2,%3}, [%4];"
                 : "=r"(r[0]), "=r"(r[1]), "=r"(r[2]), "=r"(r[3]) : "r"(addr));
}
__device__ __forceinline__ void mma16816(float* d, const uint32_t* a, const uint32_t* b) {
    asm volatile(
        "mma.sync.aligned.m16n8k16.row.col.f32.bf16.bf16.f32 "
        "{%0,%1,%2,%3},{%4,%5,%6,%7},{%8,%9},{%0,%1,%2,%3};"
        : "+f"(d[0]), "+f"(d[1]), "+f"(d[2]), "+f"(d[3])
        : "r"(a[0]), "r"(a[1]), "r"(a[2]), "r"(a[3]), "r"(b[0]), "r"(b[1]));
}
// bf16 2-term split of a float4, stored to hi/lo smem arrays at elem offset pos
__device__ __forceinline__ void split_store(bf16* hi, bf16* lo, int pos, float4 v) {
    bf162 h0 = __float22bfloat162_rn(make_float2(v.x, v.y));
    bf162 h1 = __float22bfloat162_rn(make_float2(v.z, v.w));
    float2 f0 = __bfloat1622float2(h0), f1 = __bfloat1622float2(h1);
    bf162 l0 = __float22bfloat162_rn(make_float2(v.x - f0.x, v.y - f0.y));
    bf162 l1 = __float22bfloat162_rn(make_float2(v.z - f1.x, v.w - f1.y));
    *(bf162*)(hi + pos)     = h0;
    *(bf162*)(hi + pos + 2) = h1;
    *(bf162*)(lo + pos)     = l0;
    *(bf162*)(lo + pos + 2) = l1;
}
// Single-MUFU tanh (sm_75+)
__device__ __forceinline__ float tanh_fast(float x) {
    float y;
    asm("tanh.approx.f32 %0, %1;" : "=f"(y) : "f"(x));
    return y;
}
// gate = (1 - sigmoid(zl)) * tanh(hl) = 0.5*(1 - tanh(zl/2)) * tanh(hl)
// 2 MUFU total (vs 4 MUFU + div chains for the expf form).
__device__ __forceinline__ float gate_val(float zl, float hl) {
    return 0.5f * (1.f - tanh_fast(0.5f * zl)) * tanh_fast(hl);
}

// ---------------------------------------------------------------------------
// Graph normalization + scratch zeroing (comb zeroed every replay; readout
// accumulates with atomics)
// ---------------------------------------------------------------------------
__global__ void k_zeroA() {
    int i = blockIdx.x * blockDim.x + threadIdx.x;
    if (i < NN * NN) g_A[i] = 0.f;
    if (i < NN) g_deg[i] = 1.f;
    if (i < BSZ * NL * HID) g_comb[i] = 0.f;
}
__global__ void k_deg(const int* __restrict__ edge) {
    int e = blockIdx.x * blockDim.x + threadIdx.x;
    if (e < ECNT) atomicAdd(&g_deg[edge[ECNT + e]], 1.f);
}

// ---------------------------------------------------------------------------
// Merged: adjacency build (blocks 0..65) + embedding lookup (blocks 66..1089)
// ---------------------------------------------------------------------------
#define BUILD_BLKS 66    // 66*256 = 16896 = ECNT + NN exactly
__global__ void k_build_embed(const int* __restrict__ edge,
                              const int* __restrict__ xseq,
                              const float* __restrict__ emb) {
    if (blockIdx.x < BUILD_BLKS) {
        int e = blockIdx.x * 256 + threadIdx.x;
        if (e < ECNT) {
            int s = edge[e];
            int d = edge[ECNT + e];
            atomicAdd(&g_A[d * NN + s], rsqrtf(g_deg[s]) * rsqrtf(g_deg[d]));
        } else {
            int n = e - ECNT;
            atomicAdd(&g_A[n * NN + n], 1.f / g_deg[n]);
        }
    } else {
        int t = (blockIdx.x - BUILD_BLKS) * 256 + threadIdx.x;
        int c = t & 7;
        int b = (t >> 3) & 63;
        int n = t >> 9;
        int v = xseq[(b * NN + n) * NCOL + c];
        const float4* e4 = (const float4*)(emb + ((long long)(c * VOCAB + v)) * EMBD);
        float4* o = (float4*)(g_X + (long long)n * BF + b * 128 + c * 16);
        o[0] = e4[0]; o[1] = e4[1]; o[2] = e4[2]; o[3] = e4[3];
    }
}

// ---------------------------------------------------------------------------
// Fused weight merges + merged bias (grid (2,2,7))
// ---------------------------------------------------------------------------
__global__ void __launch_bounds__(256) k_gemm64f(
    const float* __restrict__ conv_w,
    const float* __restrict__ lin_w,
    const float* __restrict__ conv_b,
    const float* __restrict__ lin_b,
    float* __restrict__ WmI)
{
    if (blockIdx.z == 6) {
        int l = blockIdx.y * 2 + blockIdx.x;
        if (l < NL) {
            int o = threadIdx.x;
            int f = o >> 1;
            int gg = (o & 1) ? 2 : 0;
            const float* cb = conv_b + (l * 3 + gg) * 128;
            const float* lw = lin_w + (l * 3 + gg) * 32768;
            float s = lin_b[(l * 3 + gg) * 128 + f];
            for (int k = 0; k < 128; k++) s += cb[k] * lw[k * 128 + f];
            g_bm[l * 256 + o] = s;
        }
        return;
    }

    const int l = blockIdx.z >> 1;
    const int half = blockIdx.z & 1;
    const int g = half ? 2 : 0;
    const float* Ag = conv_w + (l * 3 + g) * 16384;
    const float* Bg = lin_w  + (l * 3 + g) * 32768;
    float* Cg = WmI + l * 32768;

    const int tileN = blockIdx.x * 64;
    const int tileM = blockIdx.y * 64;
    __shared__ float As[16][65];
    __shared__ float Bs[16][64];
    const int tid = threadIdx.x;
    const int tx = tid & 15, ty = tid >> 4;
    float acc[4][4] = {};
    for (int k0 = 0; k0 < 128; k0 += 16) {
        #pragma unroll
        for (int i = 0; i < 4; i++) {
            int idx = tid + i * 256;
            int m = idx >> 4, k = idx & 15;
            As[k][m] = Ag[(tileM + m) * 128 + (k0 + k)];
        }
        #pragma unroll
        for (int i = 0; i < 4; i++) {
            int idx = tid + i * 256;
            int k = idx >> 6, n = idx & 63;
            Bs[k][n] = Bg[(k0 + k) * 128 + (tileN + n)];
        }
        __syncthreads();
        #pragma unroll
        for (int k = 0; k < 16; k++) {
            float a[4], b[4];
            #pragma unroll
            for (int i = 0; i < 4; i++) a[i] = As[k][ty * 4 + i];
            #pragma unroll
            for (int j = 0; j < 4; j++) b[j] = Bs[k][tx * 4 + j];
            #pragma unroll
            for (int i = 0; i < 4; i++)
                #pragma unroll
                for (int j = 0; j < 4; j++) acc[i][j] += a[i] * b[j];
        }
        __syncthreads();
    }
    #pragma unroll
    for (int i = 0; i < 4; i++)
        #pragma unroll
        for (int j = 0; j < 4; j++)
            Cg[(long long)((tileN + tx * 4 + j) * 2 + half) * 128 + (tileM + ty * 4 + i)] = acc[i][j];
}

// ---------------------------------------------------------------------------
// Tensor-core GEMM, 256 threads, 8 warps (2m x 4n), warp tile 64x32, 2 CTAs/SM.
//  BTRANS=0: B [n][k] k-contig; BTRANS=1: B [k][n] n-contig (ldmatrix.trans)
//  FUSEGATE=1: N interleaved z|h; gate -> C[m*ldc + n/2]
// fp32 operands, inline bf16 hi/lo split, 3 MMA products (hh+hl+lh).
// CTA tile 128x128, K-chunk 16, double-buffered, reg prefetch, 1 sync/chunk.
// ---------------------------------------------------------------------------
#define PA 24
#define ASZE (128 * PA)

template<int BTRANS, int FUSEGATE>
__global__ void __launch_bounds__(256, 2) k_mma(
    const float* __restrict__ A, int lda,
    const float* __restrict__ B, int ldb,
    float* __restrict__ C, int ldc,
    int K, const float* __restrict__ bias)
{
    constexpr int PB   = BTRANS ? 136 : 24;
    constexpr int BSZE = BTRANS ? 16 * 136 : 128 * 24;
    __shared__ __align__(16) bf16 smA[2][2][ASZE];
    __shared__ __align__(16) bf16 smB[2][2][BSZE];

    const int tid = threadIdx.x;
    const int lane = tid & 31, w = tid >> 5;
    const int wm = w & 1, wn = w >> 1;
    const int tileM = blockIdx.y * 128, tileN = blockIdx.x * 128;

    // loader: 2 float4 per operand per thread per 16-K chunk
    int lrow[2], lkq[2], brow2[2], bcq2[2];
    #pragma unroll
    for (int i = 0; i < 2; i++) {
        int idx = tid + i * 256;          // 0..511
        lrow[i] = idx >> 2; lkq[i] = idx & 3;                    // A: 128r x 4 f4
        if (BTRANS) { brow2[i] = idx >> 5; bcq2[i] = idx & 31; } // B: 16r x 32 f4
        else        { brow2[i] = idx >> 2; bcq2[i] = idx & 3;  } // B: 128r x 4 f4
    }

    const long long bstep = BTRANS ? 16LL * ldb : 16LL;
    const int KC = K >> 4;
    float4 ra[2], rb[2];
    #pragma unroll
    for (int i = 0; i < 2; i++) {
        ra[i] = *(const float4*)(A + (long long)(tileM + lrow[i]) * lda + lkq[i] * 4);
        if (BTRANS)
            rb[i] = *(const float4*)(B + (long long)brow2[i] * ldb + tileN + bcq2[i] * 4);
        else
            rb[i] = *(const float4*)(B + (long long)(tileN + brow2[i]) * ldb + bcq2[i] * 4);
    }

    float acc[4][4][4];
    #pragma unroll
    for (int i = 0; i < 4; i++)
        #pragma unroll
        for (int j = 0; j < 4; j++)
            #pragma unroll
            for (int q = 0; q < 4; q++) acc[i][j][q] = 0.f;

    const uint32_t sa0 = s2u(&smA[0][0][0]);
    const uint32_t sb0 = s2u(&smB[0][0][0]);
    const int arow_l = wm * 64 + (lane & 15);
    const int acol_l = (lane >> 4) * 8;
    const int brow_l = wn * 32 + ((lane >> 4) & 1) * 8 + (lane & 7);
    const int bcol_l = ((lane >> 3) & 1) * 8;
    const int tkrow_l = ((lane >> 3) & 1) * 8 + (lane & 7);
    const int tnoff_l = wn * 32 + ((lane >> 4) & 1) * 8;

    // prologue: store chunk 0 into buffer 0
    #pragma unroll
    for (int i = 0; i < 2; i++) {
        split_store(smA[0][0], smA[0][1], lrow[i] * PA + lkq[i] * 4, ra[i]);
        split_store(smB[0][0], smB[0][1], brow2[i] * PB + bcq2[i] * 4, rb[i]);
    }

    for (int c = 0; c < KC; c++) {
        __syncthreads();
        const int buf = c & 1;
        if (c + 1 < KC) {
            int kb = (c + 1) * 16;
            #pragma unroll
            for (int i = 0; i < 2; i++) {
                ra[i] = *(const float4*)(A + (long long)(tileM + lrow[i]) * lda + kb + lkq[i] * 4);
                if (BTRANS)
                    rb[i] = *(const float4*)(B + (long long)(kb + brow2[i]) * ldb + tileN + bcq2[i] * 4);
                else
                    rb[i] = *(const float4*)(B + (long long)(tileN + brow2[i]) * ldb + kb + bcq2[i] * 4);
            }
        }

        const uint32_t ba = sa0 + buf * (2 * ASZE * 2);
        const uint32_t bb = sb0 + buf * (2 * BSZE * 2);
        uint32_t ah[4][4], bh[2][4], bl[2][4];
        #pragma unroll
        for (int i = 0; i < 4; i++)
            ldsm4(ah[i], ba + (uint32_t)((arow_l + i * 16) * PA + acol_l) * 2);
        #pragma unroll
        for (int p = 0; p < 2; p++) {
            if (BTRANS) {
                ldsm4t(bh[p], bb + (uint32_t)(tkrow_l * PB + tnoff_l + p * 16) * 2);
                ldsm4t(bl[p], bb + (uint32_t)(BSZE * 2) + (uint32_t)(tkrow_l * PB + tnoff_l + p * 16) * 2);
            } else {
                ldsm4(bh[p], bb + (uint32_t)((brow_l + p * 16) * PB + bcol_l) * 2);
                ldsm4(bl[p], bb + (uint32_t)(BSZE * 2) + (uint32_t)((brow_l + p * 16) * PB + bcol_l) * 2);
            }
        }
        #pragma unroll
        for (int i = 0; i < 4; i++)
            #pragma unroll
            for (int nt = 0; nt < 4; nt++)
                mma16816(acc[i][nt], ah[i], &bh[nt >> 1][(nt & 1) * 2]);
        #pragma unroll
        for (int i = 0; i < 4; i++)
            #pragma unroll
            for (int nt = 0; nt < 4; nt++)
                mma16816(acc[i][nt], ah[i], &bl[nt >> 1][(nt & 1) * 2]);
        #pragma unroll
        for (int i = 0; i < 4; i++)     // reuse ah for A-lo
            ldsm4(ah[i], ba + (uint32_t)(ASZE * 2) + (uint32_t)((arow_l + i * 16) * PA + acol_l) * 2);
        #pragma unroll
        for (int i = 0; i < 4; i++)
            #pragma unroll
            for (int nt = 0; nt < 4; nt++)
                mma16816(acc[i][nt], ah[i], &bh[nt >> 1][(nt & 1) * 2]);

        if (c + 1 < KC) {
            const int nb = buf ^ 1;
            #pragma unroll
            for (int i = 0; i < 2; i++) {
                split_store(smA[nb][0], smA[nb][1], lrow[i] * PA + lkq[i] * 4, ra[i]);
                split_store(smB[nb][0], smB[nb][1], brow2[i] * PB + bcq2[i] * 4, rb[i]);
            }
        }
    }

    // Epilogue
    if (FUSEGATE) {
        #pragma unroll
        for (int i = 0; i < 4; i++) {
            int m = tileM + wm * 64 + i * 16 + (lane >> 2);
            #pragma unroll
            for (int nt = 0; nt < 4; nt++) {
                int n = tileN + wn * 32 + nt * 8 + (lane & 3) * 2;
                int f = n >> 1;
                float bz = bias[n], bh2 = bias[n + 1];
                C[(long long)m * ldc + f]       = gate_val(acc[i][nt][0] + bz, acc[i][nt][1] + bh2);
                C[(long long)(m + 8) * ldc + f] = gate_val(acc[i][nt][2] + bz, acc[i][nt][3] + bh2);
            }
        }
    } else {
        #pragma unroll
        for (int i = 0; i < 4; i++) {
            int m = tileM + wm * 64 + i * 16 + (lane >> 2);
            #pragma unroll
            for (int nt = 0; nt < 4; nt++) {
                int n = tileN + wn * 32 + nt * 8 + (lane & 3) * 2;
                float2 v0 = {acc[i][nt][0], acc[i][nt][1]};
                float2 v1 = {acc[i][nt][2], acc[i][nt][3]};
                *(float2*)(C + (long long)m * ldc + n)       = v0;
                *(float2*)(C + (long long)(m + 8) * ldc + n) = v1;
            }
        }
    }
}

// ---------------------------------------------------------------------------
// Readout: mean over nodes, 8-way parallel over the node dim + atomicAdd.
// g_comb zeroed every replay in k_zeroA.
// ---------------------------------------------------------------------------
__global__ void k_readout(int l) {
    int t = blockIdx.x * blockDim.x + threadIdx.x;   // 0 .. BF*8-1
    if (t >= BF * 8) return;
    int j = t & (BF - 1);
    int part = t >> 13;                  // 0..7, 64 nodes each
    float s = 0.f;
    const float* base = g_H + (long long)part * 64 * BF + j;
    #pragma unroll 8
    for (int n = 0; n < 64; n++) s += base[(long long)n * BF];
    int b = j >> 7, f = j & 127;
    atomicAdd(&g_comb[b * (NL * HID) + l * HID + f], s * (1.f / NN));
}

__global__ void k_cls(const float* __restrict__ w1, const float* __restrict__ b1,
                      const float* __restrict__ w2, const float* __restrict__ b2,
                      float* __restrict__ out) {
    int b = blockIdx.x;
    int o = threadIdx.x;
    __shared__ float hid[HID];
    float s = b1[o];
    const float* cb = g_comb + b * (NL * HID);
    for (int k = 0; k < NL * HID; k++) s += cb[k] * w1[k * HID + o];
    hid[o] = fmaxf(s, 0.f);
    __syncthreads();
    if (o < 2) {
        float t = b2[o];
        for (int k = 0; k < HID; k++) t += hid[k] * w2[k * 2 + o];
        out[b * 2 + o] = t;
    }
}

// ---------------------------------------------------------------------------
// Launch
// ---------------------------------------------------------------------------
extern "C" void kernel_launch(void* const* d_in, const int* in_sizes, int n_in,
                              void* d_out, int out_size) {
    const int*   x_seq  = (const int*)  d_in[0];
    const int*   edge   = (const int*)  d_in[1];
    const float* emb    = (const float*)d_in[2];
    const float* conv_w = (const float*)d_in[3];
    const float* conv_b = (const float*)d_in[4];
    const float* lin_w  = (const float*)d_in[5];
    const float* lin_b  = (const float*)d_in[6];
    const float* w1     = (const float*)d_in[7];
    const float* b1     = (const float*)d_in[8];
    const float* w2     = (const float*)d_in[9];
    const float* b2     = (const float*)d_in[10];
    float* out = (float*)d_out;

    float *pA, *pX, *pAX, *pH, *pWmI, *pBm;
    cudaGetSymbolAddress((void**)&pA,   g_A);
    cudaGetSymbolAddress((void**)&pX,   g_X);
    cudaGetSymbolAddress((void**)&pAX,  g_AX);
    cudaGetSymbolAddress((void**)&pH,   g_H);
    cudaGetSymbolAddress((void**)&pWmI, g_WmI);
    cudaGetSymbolAddress((void**)&pBm,  g_bm);

    // 0: zero adjacency + deg init + comb zero
    k_zeroA<<<(NN * NN + 255) / 256, 256>>>();
    // 1: degree accumulation
    k_deg<<<(ECNT + 255) / 256, 256>>>(edge);
    // 2: adjacency build + embedding (merged)
    k_build_embed<<<BUILD_BLKS + (NN * BSZ * NCOL) / 256, 256>>>(edge, x_seq, emb);

    for (int l = 0; l < NL; l++) {
        const float* xin = (l == 0) ? pX : pH;   // [n][j], ld 8192

        // GEMM1: AX[m=node][j] = sum_n A[m][n] * Xin[n][j]   (M=512,N=8192,K=512)
        k_mma<1, 0><<<dim3(64, 4), 256>>>(pA, NN, xin, BF, pAX, BF, NN, nullptr);

        if (l == 0) {
            // Weight merges + merged bias (needed before first GEMM2 only)
            k_gemm64f<<<dim3(2, 2, 7), 256>>>(conv_w, lin_w, conv_b, lin_b, pWmI);
        }

        // GEMM2 + fused gate: H[r][f]  (M=32768, N=256 interleaved, K=128)
        k_mma<0, 1><<<dim3(2, 256), 256>>>(pAX, HID, pWmI + l * 32768, HID,
                                           pH, HID, HID, pBm + l * 256);

        k_readout<<<(BF * 8 + 255) / 256, 256>>>(l);
    }

    k_cls<<<BSZ, HID>>>(w1, b1, w2, b2, out);
}